// round 14
// baseline (speedup 1.0000x reference)
#include <cuda_runtime.h>
#include <cuda_fp16.h>
#include <cstdint>

#define NTOT 16384

// ---------------- scratch globals (no allocation) ----------------
__device__ float g_pre1[NTOT * 128];   // node part of msg layer1 (+b1), fp32
__device__ float g_U[NTOT * 64];
__device__ float g_P3[8 * 256 * 256];
__device__ float g_O1[256 * 256];
__device__ __align__(16) __half g_Ah[(size_t)NTOT * 4096];          // messages (permuted), fp16
__device__ __align__(16) __half g_w1T[128 * 16];                    // edge rows of msg_w1, transposed
__device__ __align__(16) __half g_w2T[128 * 128];
__device__ __align__(16) __half g_w3T[64 * 128];
__device__ __align__(16) __half g_u1T[(size_t)256 * 4096];
__device__ __align__(16) __half g_u2T[64 * 256];

// ---------------- helpers ----------------
__device__ __forceinline__ uint32_t s2u(const void* p) {
    uint32_t a;
    asm("{ .reg .u64 t; cvta.to.shared.u64 t, %1; cvt.u32.u64 %0, t; }" : "=r"(a) : "l"(p));
    return a;
}
__device__ __forceinline__ void mmah(float* d, const uint32_t* a, const uint32_t* b) {
    asm volatile(
        "mma.sync.aligned.m16n8k16.row.col.f32.f16.f16.f32 "
        "{%0,%1,%2,%3}, {%4,%5,%6,%7}, {%8,%9}, {%0,%1,%2,%3};"
        : "+f"(d[0]), "+f"(d[1]), "+f"(d[2]), "+f"(d[3])
        : "r"(a[0]), "r"(a[1]), "r"(a[2]), "r"(a[3]), "r"(b[0]), "r"(b[1]));
}
__device__ __forceinline__ void ldm4(uint32_t* r, uint32_t a) {
    asm volatile("ldmatrix.sync.aligned.m8n8.x4.shared.b16 {%0,%1,%2,%3}, [%4];"
                 : "=r"(r[0]), "=r"(r[1]), "=r"(r[2]), "=r"(r[3]) : "r"(a));
}
__device__ __forceinline__ void cpa16(uint32_t s, const void* g) {
    asm volatile(
        "{ .reg .u64 p; cvta.to.global.u64 p, %1; cp.async.cg.shared.global [%0], [p], 16; }"
        :: "r"(s), "l"(g));
}
#define CP_COMMIT() asm volatile("cp.async.commit_group;" ::: "memory")
#define CP_WAIT1()  asm volatile("cp.async.wait_group 1;" ::: "memory")
#define CP_WAIT0()  asm volatile("cp.async.wait_group 0;" ::: "memory")
#define WSYNC()     __syncwarp()

__device__ __forceinline__ uint32_t packh2(float a, float b) {
    __half2 h = __floats2half2_rn(a, b);
    return *(uint32_t*)&h;
}

// ======================================================================
// K0: pre1[n][j] = b1[j] + node[n][:] @ W1[0:32][j]   (fp32)
// ======================================================================
__global__ void k0_pre(const float* __restrict__ node, const float* __restrict__ w1,
                       const float* __restrict__ b1) {
    __shared__ float sW[32 * 128];
    __shared__ float sB[128];
    int t = threadIdx.x;
    for (int i = t; i < 32 * 128; i += 128) sW[i] = w1[i];
    sB[t] = b1[t];
    __syncthreads();
    int row0 = blockIdx.x * 32;
    for (int r = 0; r < 32; r++) {
        int n = row0 + r;
        const float* nd = node + n * 32;
        float acc = sB[t];
#pragma unroll
        for (int k = 0; k < 32; k++) acc = fmaf(__ldg(nd + k), sW[k * 128 + t], acc);
        g_pre1[n * 128 + t] = acc;
    }
}

// ======================================================================
// Prep: small weights (w1 edge-rows, w2, w3, u2) + tiled transpose uw1
// ======================================================================
__global__ void p_small(const float* __restrict__ w1, const float* __restrict__ w2,
                        const float* __restrict__ w3, const float* __restrict__ uw2) {
    int i = blockIdx.x * 256 + threadIdx.x;
    if (i < 2048) {                                    // w1T_e [128 j][16 k] from rows 32..47
        int j = i >> 4, k = i & 15;
        g_w1T[i] = __float2half_rn(w1[(32 + k) * 128 + j]);
    } else if (i < 18432) {                            // w2T [128 j][128 k]
        int v = i - 2048, j = v >> 7, k = v & 127;
        g_w2T[v] = __float2half_rn(w2[k * 128 + j]);
    } else if (i < 26624) {                            // w3T [64 m][128 k]
        int v = i - 18432, m = v >> 7, k = v & 127;
        g_w3T[v] = __float2half_rn(w3[k * 64 + m]);
    } else if (i < 43008) {                            // u2T [64 n][256 k]
        int v = i - 26624, n = v >> 8, k = v & 255;
        g_u2T[v] = __float2half_rn(uw2[k * 64 + n]);
    }
}
__global__ void p_u1(const float* __restrict__ uw1) {  // [4096,256] -> [256,4096]
    __shared__ float s[32][33];
    int k0 = blockIdx.x * 32, n0 = blockIdx.y * 32;
    int t = threadIdx.x, r8 = t >> 5, c = t & 31;
#pragma unroll
    for (int q = 0; q < 4; q++)
        s[q * 8 + r8][c] = uw1[(size_t)(k0 + q * 8 + r8) * 256 + n0 + c];
    __syncthreads();
#pragma unroll
    for (int q = 0; q < 4; q++) {
        int n = q * 8 + r8;
        g_u1T[(size_t)(n0 + n) * 4096 + k0 + c] = __float2half_rn(s[c][n]);
    }
}

// ======================================================================
// K1: fused msg MLP via mma.sync with IN-REGISTER layer chaining.
// 512 threads / 16 warps; warp w owns rows [16w,16w+16) of a 256-edge
// tile, 2 tiles/CTA, grid 2048. The m16n8k16 C-fragment layout equals
// the next layer's A-fragment layout (a0=pack(c[2ks][0],c[2ks][1]),
// a1=pack(c[2ks][2],c[2ks][3]), a2/a3 from tile 2ks+1), so H1/H2 never
// touch smem: relu+bias applied during the in-register pack.
// Remaining smem: weights (read-only), A1 (edge feats), P1 (pre1).
// ======================================================================
#define S1_W1  0
#define S1_W2  6144
#define S1_W3  40960
#define S1_A1  58368
#define S1_P1  70656
#define S1_B2  78848
#define S1_B3  79360
#define S1_SZ  79616

__global__ void __launch_bounds__(512, 1) k1(
    const float* __restrict__ ef,
    const float* __restrict__ b2, const float* __restrict__ b3)
{
    extern __shared__ char smb[];
    uint32_t sb = s2u(smb);
    int t = threadIdx.x, wid = t >> 5, lane = t & 31;
    int qr = lane >> 2, qc = (lane & 3) * 2;
    int lane7 = lane & 7, mi = lane >> 3;
    int m0 = wid * 16;              // warp rows: 16 of 256

    // weights -> padded smem (W1/A1 stride 48B, W2/W3 stride 272B)
    for (int i = t; i < 256; i += 512) {               // W1e: 128 rows x 2 uint4
        int j = i >> 1, c = i & 1;
        *(uint4*)(smb + S1_W1 + j * 48 + c * 16) = ((const uint4*)g_w1T)[i];
    }
    for (int i = t; i < 2048; i += 512) {
        int j = i >> 4, c = i & 15;
        *(uint4*)(smb + S1_W2 + j * 272 + c * 16) = ((const uint4*)g_w2T)[i];
    }
    for (int i = t; i < 1024; i += 512) {
        int j = i >> 4, c = i & 15;
        *(uint4*)(smb + S1_W3 + j * 272 + c * 16) = ((const uint4*)g_w3T)[i];
    }
    if (t < 128) ((float*)(smb + S1_B2))[t] = b2[t];
    if (t < 64)  ((float*)(smb + S1_B3))[t] = b3[t];
    __syncthreads();   // ONLY block-wide barrier

    const float* sB2  = (const float*)(smb + S1_B2);
    const float* sB3  = (const float*)(smb + S1_B3);
    const float* sP1w = (const float*)(smb + S1_P1 + wid * 512);

    uint32_t aA1 = sb + S1_A1 + (m0 + (mi & 1) * 8 + lane7) * 48 + (mi >> 1) * 16;
    uint32_t bW1 = sb + S1_W1 + ((mi >> 1) * 8 + lane7) * 48 + (mi & 1) * 16;
    uint32_t bW2 = sb + S1_W2 + ((mi >> 1) * 8 + lane7) * 272 + (mi & 1) * 16;
    uint32_t bW3 = sb + S1_W3 + ((mi >> 1) * 8 + lane7) * 272 + (mi & 1) * 16;

#pragma unroll 1
    for (int it = 0; it < 2; it++) {
        int g0 = (blockIdx.x * 2 + it) * 4;
        WSYNC();   // this warp's prior-tile A1/P1 reads complete

        // ---- build A1 [256 x 16] fp16 (thread t -> row t>>1, warp-private) ----
        {
            int r = t >> 1, hh = t & 1;
            const float4* ep = (const float4*)(ef + (size_t)(g0 * 64 + r) * 16) + hh * 2;
            float4 e0 = __ldg(ep), e1 = __ldg(ep + 1);
            uint32_t* de = (uint32_t*)(smb + S1_A1 + r * 48 + hh * 16);
            de[0] = packh2(e0.x, e0.y); de[1] = packh2(e0.z, e0.w);
            de[2] = packh2(e1.x, e1.y); de[3] = packh2(e1.z, e1.w);
            // pre1 for this warp's source node (g uniform across the warp's rows)
            int gP = g0 + (wid >> 2);
            float4 pv = __ldg((const float4*)(g_pre1 + gP * 128) + lane);
            *(float4*)(smb + S1_P1 + wid * 512 + lane * 16) = pv;
        }
        WSYNC();

        // ---- layer1: acc = A1 @ W1eT (K=16) ----
        float acc[16][4];
#pragma unroll
        for (int n = 0; n < 16; n++)
#pragma unroll
            for (int j = 0; j < 4; j++) acc[n][j] = 0.f;
        {
            uint32_t a[4];
            ldm4(a, aA1);
#pragma unroll
            for (int np = 0; np < 8; np++) {
                uint32_t bh[4];
                ldm4(bh, bW1 + np * 768);              // 16 rows * 48B per np
                mmah(acc[2 * np], a, bh);
                mmah(acc[2 * np + 1], a, bh + 2);
            }
        }
        // convert1 (in-register): aF = relu(acc + pre1) as layer2 A-fragments
        uint32_t aF[32];
#pragma unroll
        for (int nt = 0; nt < 16; nt++) {
            int c0 = nt * 8 + qc;
            float v0 = sP1w[c0], v1 = sP1w[c0 + 1];
            aF[(nt >> 1) * 4 + (nt & 1) * 2 + 0] =
                packh2(fmaxf(acc[nt][0] + v0, 0.f), fmaxf(acc[nt][1] + v1, 0.f));
            aF[(nt >> 1) * 4 + (nt & 1) * 2 + 1] =
                packh2(fmaxf(acc[nt][2] + v0, 0.f), fmaxf(acc[nt][3] + v1, 0.f));
        }

        // ---- layer2: acc = H1 @ W2T (K=128), A from registers ----
#pragma unroll
        for (int n = 0; n < 16; n++)
#pragma unroll
            for (int j = 0; j < 4; j++) acc[n][j] = 0.f;
#pragma unroll 1
        for (int ks = 0; ks < 8; ks++) {
            const uint32_t* a = &aF[ks * 4];
#pragma unroll
            for (int np = 0; np < 8; np++) {
                uint32_t bh[4];
                ldm4(bh, bW2 + np * 4352 + ks * 32);   // 16 rows * 272B per np
                mmah(acc[2 * np], a, bh);
                mmah(acc[2 * np + 1], a, bh + 2);
            }
        }
        // convert2 (in-register): aF = relu(acc + b2) as layer3 A-fragments
#pragma unroll
        for (int nt = 0; nt < 16; nt++) {
            int c0 = nt * 8 + qc;
            float v0 = sB2[c0], v1 = sB2[c0 + 1];
            aF[(nt >> 1) * 4 + (nt & 1) * 2 + 0] =
                packh2(fmaxf(acc[nt][0] + v0, 0.f), fmaxf(acc[nt][1] + v1, 0.f));
            aF[(nt >> 1) * 4 + (nt & 1) * 2 + 1] =
                packh2(fmaxf(acc[nt][2] + v0, 0.f), fmaxf(acc[nt][3] + v1, 0.f));
        }

        // ---- layer3: acc2 = H2 @ W3T (K=128, N=64), A from registers ----
        float acc2[8][4];
#pragma unroll
        for (int n = 0; n < 8; n++)
#pragma unroll
            for (int j = 0; j < 4; j++) acc2[n][j] = 0.f;
#pragma unroll 1
        for (int ks = 0; ks < 8; ks++) {
            const uint32_t* a = &aF[ks * 4];
#pragma unroll
            for (int np = 0; np < 4; np++) {
                uint32_t bh[4];
                ldm4(bh, bW3 + np * 4352 + ks * 32);   // 16 rows * 272B per np
                mmah(acc2[2 * np], a, bh);
                mmah(acc2[2 * np + 1], a, bh + 2);
            }
        }
        // epi3: msg + b3 -> g_Ah (permuted scatter), fp16
#pragma unroll
        for (int h = 0; h < 2; h++) {
            int d = m0 + qr + h * 8;
            int g = g0 + (d >> 6);
            size_t base = ((size_t)((g >> 6) * 64 + (d & 63))) * 4096 + (g & 63) * 64;
#pragma unroll
            for (int nt = 0; nt < 8; nt++) {
                int c0 = nt * 8 + qc;
                *(uint32_t*)(g_Ah + base + c0) =
                    packh2(acc2[nt][h * 2 + 0] + sB3[c0],
                           acc2[nt][h * 2 + 1] + sB3[c0 + 1]);
            }
        }
    }
}

// ======================================================================
// K2: C = relu(A @ uw1 + ub1) [16384x4096 @ 4096x256], then fused
//     U = C @ uw2 + ub2 -> g_U. grid 128 x 512 threads. K-chunk 64,
//     3-stage cp.async pipeline, ONE __syncthreads per iteration.
// ======================================================================
#define S2_A   0
#define S2_B   18432
#define S2_STG 55296
#define S2_C   0
#define S2_U2  67584
#define S2_SZ  165888

__global__ void __launch_bounds__(512, 1) k2(
    const float* __restrict__ ub1, const float* __restrict__ ub2)
{
    extern __shared__ char smb[];
    uint32_t sb = s2u(smb);
    int t = threadIdx.x, wid = t >> 5, lane = t & 31;
    int qr = lane >> 2, qc = (lane & 3) * 2;
    int lane7 = lane & 7, mi = lane >> 3;
    int row0 = blockIdx.x * 128;
    int wm = (wid >> 2) * 32, wn = (wid & 3) * 64;

    auto fill = [&](int kc, uint32_t stg) {
#pragma unroll
        for (int q = 0; q < 2; q++) {
            int i = q * 512 + t, r = i >> 3, c = i & 7;
            cpa16(sb + stg + S2_A + r * 144 + c * 16,
                  g_Ah + (size_t)(row0 + r) * 4096 + kc * 64 + c * 8);
        }
#pragma unroll
        for (int q = 0; q < 4; q++) {
            int i = q * 512 + t, n = i >> 3, c = i & 7;
            cpa16(sb + stg + S2_B + n * 144 + c * 16,
                  g_u1T + (size_t)n * 4096 + kc * 64 + c * 8);
        }
    };

    float acc[2][8][4];
#pragma unroll
    for (int m = 0; m < 2; m++)
#pragma unroll
        for (int n = 0; n < 8; n++)
#pragma unroll
            for (int j = 0; j < 4; j++) acc[m][n][j] = 0.f;

    fill(0, 0);
    CP_COMMIT();
    fill(1, S2_STG);
    CP_COMMIT();

    int st = 0;
#pragma unroll 1
    for (int kc = 0; kc < 64; kc++) {
        if (kc + 1 < 64) CP_WAIT1(); else CP_WAIT0();  // fill(kc) complete
        __syncthreads();                               // all warps done with compute(kc-1)
        if (kc + 2 < 64) {
            fill(kc + 2, (uint32_t)((kc + 2) % 3) * S2_STG);
            CP_COMMIT();
        }
        uint32_t stg = (uint32_t)st * S2_STG;
        uint32_t aA = sb + stg + S2_A + (wm + (mi & 1) * 8 + lane7) * 144 + (mi >> 1) * 16;
        uint32_t bB = sb + stg + S2_B + (wn + (mi >> 1) * 8 + lane7) * 144 + (mi & 1) * 16;
#pragma unroll
        for (int ks = 0; ks < 4; ks++) {
            uint32_t a0[4], a1[4];
            ldm4(a0, aA + ks * 32);
            ldm4(a1, aA + 2304 + ks * 32);          // +16 rows * 144B
#pragma unroll
            for (int np = 0; np < 4; np++) {
                uint32_t bh[4];
                ldm4(bh, bB + np * 2304 + ks * 32); // 16 n-rows * 144B per np
                mmah(acc[0][2 * np], a0, bh);
                mmah(acc[0][2 * np + 1], a0, bh + 2);
                mmah(acc[1][2 * np], a1, bh);
                mmah(acc[1][2 * np + 1], a1, bh + 2);
            }
        }
        st = (st == 2) ? 0 : st + 1;
    }

    // ---- epilogue: C = relu(acc + ub1) -> smem fp16, then U = C @ uw2T + ub2 ----
    __syncthreads();   // all warps finished mainloop reads before C overwrites stages
#pragma unroll
    for (int ms = 0; ms < 2; ms++)
#pragma unroll
        for (int h = 0; h < 2; h++) {
            int rr = wm + ms * 16 + qr + h * 8;
#pragma unroll
            for (int ns = 0; ns < 8; ns++) {
                int c = wn + ns * 8 + qc;
                *(uint32_t*)(smb + S2_C + rr * 528 + c * 2) =
                    packh2(fmaxf(acc[ms][ns][h * 2 + 0] + __ldg(ub1 + c), 0.f),
                           fmaxf(acc[ms][ns][h * 2 + 1] + __ldg(ub1 + c + 1), 0.f));
            }
        }
    // uw2T -> smem: [64 n][256 k] halfs = 2048 uint4, 32 uint4/row, stride 528B
    for (int i = t; i < 2048; i += 512) {
        int n = i >> 5, c = i & 31;
        *(uint4*)(smb + S2_U2 + n * 528 + c * 16) = ((const uint4*)g_u2T)[i];
    }
    __syncthreads();

    int wm2 = (wid >> 2) * 32, wn2 = (wid & 3) * 16;
    float au[2][2][4];
#pragma unroll
    for (int m = 0; m < 2; m++)
#pragma unroll
        for (int n = 0; n < 2; n++)
#pragma unroll
            for (int j = 0; j < 4; j++) au[m][n][j] = 0.f;
    uint32_t aC = sb + S2_C + (wm2 + (mi & 1) * 8 + lane7) * 528 + (mi >> 1) * 16;
    uint32_t b2a = sb + S2_U2 + (wn2 + (mi >> 1) * 8 + lane7) * 528 + (mi & 1) * 16;
#pragma unroll 1
    for (int ks = 0; ks < 16; ks++) {
        uint32_t a0[4], a1[4], bh[4];
        ldm4(a0, aC + ks * 32);
        ldm4(a1, aC + 16 * 528 + ks * 32);
        ldm4(bh, b2a + ks * 32);
        mmah(au[0][0], a0, bh);
        mmah(au[0][1], a0, bh + 2);
        mmah(au[1][0], a1, bh);
        mmah(au[1][1], a1, bh + 2);
    }
#pragma unroll
    for (int mt = 0; mt < 2; mt++)
#pragma unroll
        for (int h = 0; h < 2; h++) {
            int rr = row0 + wm2 + mt * 16 + qr + h * 8;
#pragma unroll
            for (int nt = 0; nt < 2; nt++) {
                int c = wn2 + nt * 8 + qc;
                float2 v;
                v.x = au[mt][nt][h * 2 + 0] + __ldg(ub2 + c);
                v.y = au[mt][nt][h * 2 + 1] + __ldg(ub2 + c + 1);
                *(float2*)&g_U[(size_t)rr * 64 + c] = v;
            }
        }
}

// ======================================================================
// K3a/b + K4: out head (fp32)
// ======================================================================
__global__ void k3a_gemm(const float* __restrict__ w) {
    __shared__ float sUT[32 * 68];
    __shared__ float sWt[32 * 64];
    int t = threadIdx.x;
    int ty = t >> 4, tx = t & 15;
    int m0 = blockIdx.x * 64, n0 = blockIdx.y * 64, p = blockIdx.z;
    int k0 = p * 512;
    float acc[4][4];
#pragma unroll
    for (int i = 0; i < 4; i++)
#pragma unroll
        for (int j = 0; j < 4; j++) acc[i][j] = 0.f;
    for (int kt = 0; kt < 16; kt++) {
#pragma unroll
        for (int q = 0; q < 2; q++) {
            int f = q * 256 + t, r = f >> 3, c4 = f & 7;
            float4 v = *(const float4*)&g_U[(size_t)(m0 + r) * 4096 + k0 + kt * 32 + c4 * 4];
            sUT[(c4 * 4 + 0) * 68 + r] = v.x;
            sUT[(c4 * 4 + 1) * 68 + r] = v.y;
            sUT[(c4 * 4 + 2) * 68 + r] = v.z;
            sUT[(c4 * 4 + 3) * 68 + r] = v.w;
        }
#pragma unroll
        for (int q = 0; q < 2; q++) {
            int f = q * 256 + t, kr = f >> 4, c4 = f & 15;
            *(float4*)&sWt[kr * 64 + c4 * 4] =
                *(const float4*)&w[(size_t)(k0 + kt * 32 + kr) * 256 + n0 + c4 * 4];
        }
        __syncthreads();
#pragma unroll 4
        for (int k = 0; k < 32; k++) {
            float4 a = *(float4*)&sUT[k * 68 + ty * 4];
            float4 b = *(float4*)&sWt[k * 64 + tx * 4];
            float av[4] = {a.x, a.y, a.z, a.w};
            float bv[4] = {b.x, b.y, b.z, b.w};
#pragma unroll
            for (int i = 0; i < 4; i++)
#pragma unroll
                for (int j = 0; j < 4; j++) acc[i][j] = fmaf(av[i], bv[j], acc[i][j]);
        }
        __syncthreads();
    }
#pragma unroll
    for (int i = 0; i < 4; i++) {
        int m = m0 + ty * 4 + i;
        *(float4*)&g_P3[(size_t)p * 65536 + m * 256 + n0 + tx * 4] =
            make_float4(acc[i][0], acc[i][1], acc[i][2], acc[i][3]);
    }
}
__global__ void k3b_reduce(const float* __restrict__ b1) {
    int m = blockIdx.x, n = threadIdx.x;
    float acc = b1[n];
#pragma unroll
    for (int p = 0; p < 8; p++) acc += g_P3[p * 65536 + m * 256 + n];
    g_O1[m * 256 + n] = fmaxf(acc, 0.f);
}
__global__ void k4_final(const float* __restrict__ w2, const float* __restrict__ b2,
                         float* __restrict__ out) {
    __shared__ float sW[256];
    int t = threadIdx.x;
    sW[t] = w2[t];
    __syncthreads();
    int lane = t & 31, wid = t >> 5;
    int r0 = blockIdx.x * 32 + wid * 4;
    for (int r = r0; r < r0 + 4; r++) {
        float acc = 0.f;
#pragma unroll
        for (int k = lane; k < 256; k += 32) acc = fmaf(g_O1[r * 256 + k], sW[k], acc);
#pragma unroll
        for (int off = 16; off; off >>= 1) acc += __shfl_xor_sync(0xffffffffu, acc, off);
        if (lane == 0) out[r] = acc + b2[0];
    }
}

// ======================================================================
extern "C" void kernel_launch(void* const* d_in, const int* in_sizes, int n_in,
                              void* d_out, int out_size) {
    const float* node = (const float*)d_in[0];
    const float* ef   = (const float*)d_in[1];
    const float* mw1 = (const float*)d_in[3];
    const float* mb1 = (const float*)d_in[4];
    const float* mw2 = (const float*)d_in[5];
    const float* mb2 = (const float*)d_in[6];
    const float* mw3 = (const float*)d_in[7];
    const float* mb3 = (const float*)d_in[8];
    const float* uw1 = (const float*)d_in[9];
    const float* ub1 = (const float*)d_in[10];
    const float* uw2 = (const float*)d_in[11];
    const float* ub2 = (const float*)d_in[12];
    const float* ow1 = (const float*)d_in[13];
    const float* ob1 = (const float*)d_in[14];
    const float* ow2 = (const float*)d_in[15];
    const float* ob2 = (const float*)d_in[16];
    float* out = (float*)d_out;

    cudaFuncSetAttribute(k1, cudaFuncAttributeMaxDynamicSharedMemorySize, S1_SZ);
    cudaFuncSetAttribute(k2, cudaFuncAttributeMaxDynamicSharedMemorySize, S2_SZ);

    k0_pre<<<512, 128>>>(node, mw1, mb1);
    p_small<<<168, 256>>>(mw1, mw2, mw3, uw2);
    p_u1<<<dim3(128, 8), 256>>>(uw1);
    k1<<<2048, 512, S1_SZ>>>(ef, mb2, mb3);
    k2<<<128, 512, S2_SZ>>>(ub1, ub2);
    dim3 g3(4, 4, 8);
    k3a_gemm<<<g3, 256>>>(ow1);
    k3b_reduce<<<256, 256>>>(ob1);
    k4_final<<<8, 256>>>(ow2, ob2, out);
}

// round 15
// speedup vs baseline: 1.1066x; 1.1066x over previous
#include <cuda_runtime.h>
#include <cuda_fp16.h>
#include <cstdint>

#define NTOT 16384

// ---------------- scratch globals (no allocation) ----------------
__device__ float g_pre1[NTOT * 128];   // node part of msg layer1 (+b1), fp32
__device__ float g_U[NTOT * 64];
__device__ float g_P3[8 * 256 * 256];
__device__ float g_O1[256 * 256];
__device__ __align__(16) __half g_Ah[(size_t)NTOT * 4096];          // messages (permuted), fp16
__device__ __align__(16) __half g_w1T[128 * 16];                    // edge rows of msg_w1, transposed
__device__ __align__(16) __half g_w2T[128 * 128];
__device__ __align__(16) __half g_w3T[64 * 128];
__device__ __align__(16) __half g_u1T[(size_t)256 * 4096];
__device__ __align__(16) __half g_u2T[64 * 256];

// ---------------- helpers ----------------
__device__ __forceinline__ uint32_t s2u(const void* p) {
    uint32_t a;
    asm("{ .reg .u64 t; cvta.to.shared.u64 t, %1; cvt.u32.u64 %0, t; }" : "=r"(a) : "l"(p));
    return a;
}
__device__ __forceinline__ void mmah(float* d, const uint32_t* a, const uint32_t* b) {
    asm volatile(
        "mma.sync.aligned.m16n8k16.row.col.f32.f16.f16.f32 "
        "{%0,%1,%2,%3}, {%4,%5,%6,%7}, {%8,%9}, {%0,%1,%2,%3};"
        : "+f"(d[0]), "+f"(d[1]), "+f"(d[2]), "+f"(d[3])
        : "r"(a[0]), "r"(a[1]), "r"(a[2]), "r"(a[3]), "r"(b[0]), "r"(b[1]));
}
__device__ __forceinline__ void ldm4(uint32_t* r, uint32_t a) {
    asm volatile("ldmatrix.sync.aligned.m8n8.x4.shared.b16 {%0,%1,%2,%3}, [%4];"
                 : "=r"(r[0]), "=r"(r[1]), "=r"(r[2]), "=r"(r[3]) : "r"(a));
}
__device__ __forceinline__ void cpa16(uint32_t s, const void* g) {
    asm volatile(
        "{ .reg .u64 p; cvta.to.global.u64 p, %1; cp.async.cg.shared.global [%0], [p], 16; }"
        :: "r"(s), "l"(g));
}
#define CP_COMMIT() asm volatile("cp.async.commit_group;" ::: "memory")
#define CP_WAIT1()  asm volatile("cp.async.wait_group 1;" ::: "memory")
#define CP_WAIT0()  asm volatile("cp.async.wait_group 0;" ::: "memory")
// pair barrier: 64 threads of warp-pair 'pid' (ids 1..8)
#define PSYNC(pid) asm volatile("bar.sync %0, 64;" :: "r"((pid) + 1) : "memory")

__device__ __forceinline__ uint32_t packh2(float a, float b) {
    __half2 h = __floats2half2_rn(a, b);
    return *(uint32_t*)&h;
}

// ======================================================================
// K0: pre1[n][j] = b1[j] + node[n][:] @ W1[0:32][j]   (fp32)
// ======================================================================
__global__ void k0_pre(const float* __restrict__ node, const float* __restrict__ w1,
                       const float* __restrict__ b1) {
    __shared__ float sW[32 * 128];
    __shared__ float sB[128];
    int t = threadIdx.x;
    for (int i = t; i < 32 * 128; i += 128) sW[i] = w1[i];
    sB[t] = b1[t];
    __syncthreads();
    int row0 = blockIdx.x * 32;
    for (int r = 0; r < 32; r++) {
        int n = row0 + r;
        const float* nd = node + n * 32;
        float acc = sB[t];
#pragma unroll
        for (int k = 0; k < 32; k++) acc = fmaf(__ldg(nd + k), sW[k * 128 + t], acc);
        g_pre1[n * 128 + t] = acc;
    }
}

// ======================================================================
// Prep: small weights (w1 edge-rows, w2, w3, u2) + tiled transpose uw1
// ======================================================================
__global__ void p_small(const float* __restrict__ w1, const float* __restrict__ w2,
                        const float* __restrict__ w3, const float* __restrict__ uw2) {
    int i = blockIdx.x * 256 + threadIdx.x;
    if (i < 2048) {                                    // w1T_e [128 j][16 k] from rows 32..47
        int j = i >> 4, k = i & 15;
        g_w1T[i] = __float2half_rn(w1[(32 + k) * 128 + j]);
    } else if (i < 18432) {                            // w2T [128 j][128 k]
        int v = i - 2048, j = v >> 7, k = v & 127;
        g_w2T[v] = __float2half_rn(w2[k * 128 + j]);
    } else if (i < 26624) {                            // w3T [64 m][128 k]
        int v = i - 18432, m = v >> 7, k = v & 127;
        g_w3T[v] = __float2half_rn(w3[k * 64 + m]);
    } else if (i < 43008) {                            // u2T [64 n][256 k]
        int v = i - 26624, n = v >> 8, k = v & 255;
        g_u2T[v] = __float2half_rn(uw2[k * 64 + n]);
    }
}
__global__ void p_u1(const float* __restrict__ uw1) {  // [4096,256] -> [256,4096]
    __shared__ float s[32][33];
    int k0 = blockIdx.x * 32, n0 = blockIdx.y * 32;
    int t = threadIdx.x, r8 = t >> 5, c = t & 31;
#pragma unroll
    for (int q = 0; q < 4; q++)
        s[q * 8 + r8][c] = uw1[(size_t)(k0 + q * 8 + r8) * 256 + n0 + c];
    __syncthreads();
#pragma unroll
    for (int q = 0; q < 4; q++) {
        int n = q * 8 + r8;
        g_u1T[(size_t)(n0 + n) * 4096 + k0 + c] = __float2half_rn(s[c][n]);
    }
}

// ======================================================================
// K1: fused msg MLP. 512 threads / 16 warps / 8 PAIRS; pair p owns rows
// [32p,32p+32) of a 256-edge tile (2 tiles/CTA, grid 2048). Even warp
// computes cols [0,64) (l1/l2) or [0,32) (l3); odd warp the upper half
// (B-fragment traffic halved = R13 win). The warp's own output cols are
// exactly A-fragment ks range [4nh,4nh+4) of the next layer -> chain own
// half in registers (R14-validated mapping), read only the PARTNER half
// via ldmatrix (A-ldm4 halves). Each layer: epi -> own-ks MMAs -> PSYNC
// -> partner-ks MMAs (barrier hidden behind independent MMAs).
// ======================================================================
#define S1_W1  0
#define S1_W2  6144
#define S1_W3  40960
#define S1_H1  58368
#define S1_A1  128000
#define S1_P1  140288
#define S1_B2  144384
#define S1_B3  144896
#define S1_SZ  145408

__global__ void __launch_bounds__(512, 1) k1(
    const float* __restrict__ ef,
    const float* __restrict__ b2, const float* __restrict__ b3)
{
    extern __shared__ char smb[];
    uint32_t sb = s2u(smb);
    int t = threadIdx.x, wid = t >> 5, lane = t & 31;
    int qr = lane >> 2, qc = (lane & 3) * 2;
    int lane7 = lane & 7, mi = lane >> 3;
    int pair = wid >> 1, nh = wid & 1;
    int m0 = pair * 32;

    // weights -> padded smem
    for (int i = t; i < 256; i += 512) {
        int j = i >> 1, c = i & 1;
        *(uint4*)(smb + S1_W1 + j * 48 + c * 16) = ((const uint4*)g_w1T)[i];
    }
    for (int i = t; i < 2048; i += 512) {
        int j = i >> 4, c = i & 15;
        *(uint4*)(smb + S1_W2 + j * 272 + c * 16) = ((const uint4*)g_w2T)[i];
    }
    for (int i = t; i < 1024; i += 512) {
        int j = i >> 4, c = i & 15;
        *(uint4*)(smb + S1_W3 + j * 272 + c * 16) = ((const uint4*)g_w3T)[i];
    }
    if (t < 128) ((float*)(smb + S1_B2))[t] = b2[t];
    if (t < 64)  ((float*)(smb + S1_B3))[t] = b3[t];
    __syncthreads();

    const float* sB2  = (const float*)(smb + S1_B2);
    const float* sB3  = (const float*)(smb + S1_B3);
    const float* sP1p = (const float*)(smb + S1_P1 + pair * 512);

    uint32_t aA1 = sb + S1_A1 + (m0 + (mi & 1) * 8 + lane7) * 48 + (mi >> 1) * 16;
    uint32_t aH1 = sb + S1_H1 + (m0 + (mi & 1) * 8 + lane7) * 272 + (mi >> 1) * 16;
    uint32_t bW1 = sb + S1_W1 + (nh * 64 + (mi >> 1) * 8 + lane7) * 48 + (mi & 1) * 16;
    uint32_t bW2 = sb + S1_W2 + (nh * 64 + (mi >> 1) * 8 + lane7) * 272 + (mi & 1) * 16;
    uint32_t bW3 = sb + S1_W3 + (nh * 32 + (mi >> 1) * 8 + lane7) * 272 + (mi & 1) * 16;
    int ks_own0 = 4 * nh, ks_par0 = 4 * (1 - nh);

#pragma unroll 1
    for (int it = 0; it < 2; it++) {
        int g0 = (blockIdx.x * 2 + it) * 4;
        PSYNC(pair);   // pair's prior-tile A1/P1/H reads complete

        // ---- build A1 [256 x 16] fp16 (thread t -> row t>>1) + P1 fill ----
        {
            int r = t >> 1, hh = t & 1;
            const float4* ep = (const float4*)(ef + (size_t)(g0 * 64 + r) * 16) + hh * 2;
            float4 e0 = __ldg(ep), e1 = __ldg(ep + 1);
            uint32_t* de = (uint32_t*)(smb + S1_A1 + r * 48 + hh * 16);
            de[0] = packh2(e0.x, e0.y); de[1] = packh2(e0.z, e0.w);
            de[2] = packh2(e1.x, e1.y); de[3] = packh2(e1.z, e1.w);
            if (nh == 0) {   // even warp loads the pair's pre1 row
                int gP = g0 + (pair >> 1);
                float4 pv = __ldg((const float4*)(g_pre1 + gP * 128) + lane);
                *(float4*)(smb + S1_P1 + pair * 512 + lane * 16) = pv;
            }
        }
        PSYNC(pair);   // A1 rows + P1 visible to both warps of the pair

        // ---- layer1: acc = A1 @ W1eT (K=16, own n-half) ----
        float acc[2][8][4];
#pragma unroll
        for (int m = 0; m < 2; m++)
#pragma unroll
            for (int n = 0; n < 8; n++)
#pragma unroll
                for (int j = 0; j < 4; j++) acc[m][n][j] = 0.f;
        {
            uint32_t a0[4], a1[4];
            ldm4(a0, aA1);
            ldm4(a1, aA1 + 16 * 48);
#pragma unroll
            for (int np = 0; np < 4; np++) {
                uint32_t bh[4];
                ldm4(bh, bW1 + np * 768);
                mmah(acc[0][2 * np], a0, bh);
                mmah(acc[0][2 * np + 1], a0, bh + 2);
                mmah(acc[1][2 * np], a1, bh);
                mmah(acc[1][2 * np + 1], a1, bh + 2);
            }
        }
        // epi1: H1 = relu(acc + pre1); write own half to smem, keep chain regs
        uint32_t aF[2][16];
#pragma unroll
        for (int mf = 0; mf < 2; mf++) {
            int r0 = m0 + mf * 16 + qr;
#pragma unroll
            for (int nt = 0; nt < 8; nt++) {
                int c0 = nh * 64 + nt * 8 + qc;
                float v0 = sP1p[c0], v1 = sP1p[c0 + 1];
                uint32_t lo = packh2(fmaxf(acc[mf][nt][0] + v0, 0.f),
                                     fmaxf(acc[mf][nt][1] + v1, 0.f));
                uint32_t hi = packh2(fmaxf(acc[mf][nt][2] + v0, 0.f),
                                     fmaxf(acc[mf][nt][3] + v1, 0.f));
                *(uint32_t*)(smb + S1_H1 + r0 * 272 + c0 * 2) = lo;
                *(uint32_t*)(smb + S1_H1 + (r0 + 8) * 272 + c0 * 2) = hi;
                aF[mf][(nt >> 1) * 4 + (nt & 1) * 2 + 0] = lo;
                aF[mf][(nt >> 1) * 4 + (nt & 1) * 2 + 1] = hi;
            }
        }

        // ---- layer2 own-ks (A from registers) ----
#pragma unroll
        for (int m = 0; m < 2; m++)
#pragma unroll
            for (int n = 0; n < 8; n++)
#pragma unroll
                for (int j = 0; j < 4; j++) acc[m][n][j] = 0.f;
#pragma unroll
        for (int ts = 0; ts < 4; ts++) {
            int ks = ks_own0 + ts;
#pragma unroll
            for (int np = 0; np < 4; np++) {
                uint32_t bh[4];
                ldm4(bh, bW2 + np * 4352 + ks * 32);
                mmah(acc[0][2 * np], &aF[0][ts * 4], bh);
                mmah(acc[0][2 * np + 1], &aF[0][ts * 4], bh + 2);
                mmah(acc[1][2 * np], &aF[1][ts * 4], bh);
                mmah(acc[1][2 * np + 1], &aF[1][ts * 4], bh + 2);
            }
        }
        PSYNC(pair);   // partner's H1 half written (its epi1 precedes its own-ks work)
        // ---- layer2 partner-ks (A via ldmatrix) ----
#pragma unroll
        for (int ts = 0; ts < 4; ts++) {
            int ks = ks_par0 + ts;
            uint32_t p0[4], p1[4];
            ldm4(p0, aH1 + ks * 32);
            ldm4(p1, aH1 + 4352 + ks * 32);
#pragma unroll
            for (int np = 0; np < 4; np++) {
                uint32_t bh[4];
                ldm4(bh, bW2 + np * 4352 + ks * 32);
                mmah(acc[0][2 * np], p0, bh);
                mmah(acc[0][2 * np + 1], p0, bh + 2);
                mmah(acc[1][2 * np], p1, bh);
                mmah(acc[1][2 * np + 1], p1, bh + 2);
            }
        }
        PSYNC(pair);   // both warps done reading H1 before H2 overwrite

        // epi2: H2 = relu(acc + b2); write own half, keep chain regs
#pragma unroll
        for (int mf = 0; mf < 2; mf++) {
            int r0 = m0 + mf * 16 + qr;
#pragma unroll
            for (int nt = 0; nt < 8; nt++) {
                int c0 = nh * 64 + nt * 8 + qc;
                float v0 = sB2[c0], v1 = sB2[c0 + 1];
                uint32_t lo = packh2(fmaxf(acc[mf][nt][0] + v0, 0.f),
                                     fmaxf(acc[mf][nt][1] + v1, 0.f));
                uint32_t hi = packh2(fmaxf(acc[mf][nt][2] + v0, 0.f),
                                     fmaxf(acc[mf][nt][3] + v1, 0.f));
                *(uint32_t*)(smb + S1_H1 + r0 * 272 + c0 * 2) = lo;
                *(uint32_t*)(smb + S1_H1 + (r0 + 8) * 272 + c0 * 2) = hi;
                aF[mf][(nt >> 1) * 4 + (nt & 1) * 2 + 0] = lo;
                aF[mf][(nt >> 1) * 4 + (nt & 1) * 2 + 1] = hi;
            }
        }

        // ---- layer3 own-ks (A from registers) ----
        float acc2[2][4][4];
#pragma unroll
        for (int m = 0; m < 2; m++)
#pragma unroll
            for (int n = 0; n < 4; n++)
#pragma unroll
                for (int j = 0; j < 4; j++) acc2[m][n][j] = 0.f;
#pragma unroll
        for (int ts = 0; ts < 4; ts++) {
            int ks = ks_own0 + ts;
#pragma unroll
            for (int np = 0; np < 2; np++) {
                uint32_t bh[4];
                ldm4(bh, bW3 + np * 4352 + ks * 32);
                mmah(acc2[0][2 * np], &aF[0][ts * 4], bh);
                mmah(acc2[0][2 * np + 1], &aF[0][ts * 4], bh + 2);
                mmah(acc2[1][2 * np], &aF[1][ts * 4], bh);
                mmah(acc2[1][2 * np + 1], &aF[1][ts * 4], bh + 2);
            }
        }
        PSYNC(pair);   // partner's H2 half written
        // ---- layer3 partner-ks ----
#pragma unroll
        for (int ts = 0; ts < 4; ts++) {
            int ks = ks_par0 + ts;
            uint32_t p0[4], p1[4];
            ldm4(p0, aH1 + ks * 32);
            ldm4(p1, aH1 + 4352 + ks * 32);
#pragma unroll
            for (int np = 0; np < 2; np++) {
                uint32_t bh[4];
                ldm4(bh, bW3 + np * 4352 + ks * 32);
                mmah(acc2[0][2 * np], p0, bh);
                mmah(acc2[0][2 * np + 1], p0, bh + 2);
                mmah(acc2[1][2 * np], p1, bh);
                mmah(acc2[1][2 * np + 1], p1, bh + 2);
            }
        }
        // epi3: msg + b3 -> g_Ah (permuted scatter), fp16
        {
            int g = g0 + (pair >> 1);
            size_t gb = ((size_t)((g >> 6) * 64)) * 4096 + (g & 63) * 64;
#pragma unroll
            for (int mf = 0; mf < 2; mf++)
#pragma unroll
                for (int h = 0; h < 2; h++) {
                    int d = (m0 + mf * 16 + qr + h * 8) & 63;
                    size_t base = gb + (size_t)d * 4096;
#pragma unroll
                    for (int nt = 0; nt < 4; nt++) {
                        int c0 = nh * 32 + nt * 8 + qc;
                        *(uint32_t*)(g_Ah + base + c0) =
                            packh2(acc2[mf][nt][h * 2 + 0] + sB3[c0],
                                   acc2[mf][nt][h * 2 + 1] + sB3[c0 + 1]);
                    }
                }
        }
    }
}

// ======================================================================
// K2: C = relu(A @ uw1 + ub1), fused U = C @ uw2 + ub2 -> g_U.
// grid 128 x 512. K-chunk 64, 3-stage cp.async, one sync/iter.
// ======================================================================
#define S2_A   0
#define S2_B   18432
#define S2_STG 55296
#define S2_C   0
#define S2_U2  67584
#define S2_SZ  165888

__global__ void __launch_bounds__(512, 1) k2(
    const float* __restrict__ ub1, const float* __restrict__ ub2)
{
    extern __shared__ char smb[];
    uint32_t sb = s2u(smb);
    int t = threadIdx.x, wid = t >> 5, lane = t & 31;
    int qr = lane >> 2, qc = (lane & 3) * 2;
    int lane7 = lane & 7, mi = lane >> 3;
    int row0 = blockIdx.x * 128;
    int wm = (wid >> 2) * 32, wn = (wid & 3) * 64;

    auto fill = [&](int kc, uint32_t stg) {
#pragma unroll
        for (int q = 0; q < 2; q++) {
            int i = q * 512 + t, r = i >> 3, c = i & 7;
            cpa16(sb + stg + S2_A + r * 144 + c * 16,
                  g_Ah + (size_t)(row0 + r) * 4096 + kc * 64 + c * 8);
        }
#pragma unroll
        for (int q = 0; q < 4; q++) {
            int i = q * 512 + t, n = i >> 3, c = i & 7;
            cpa16(sb + stg + S2_B + n * 144 + c * 16,
                  g_u1T + (size_t)n * 4096 + kc * 64 + c * 8);
        }
    };

    float acc[2][8][4];
#pragma unroll
    for (int m = 0; m < 2; m++)
#pragma unroll
        for (int n = 0; n < 8; n++)
#pragma unroll
            for (int j = 0; j < 4; j++) acc[m][n][j] = 0.f;

    fill(0, 0);
    CP_COMMIT();
    fill(1, S2_STG);
    CP_COMMIT();

    int st = 0;
#pragma unroll 1
    for (int kc = 0; kc < 64; kc++) {
        if (kc + 1 < 64) CP_WAIT1(); else CP_WAIT0();
        __syncthreads();
        if (kc + 2 < 64) {
            fill(kc + 2, (uint32_t)((kc + 2) % 3) * S2_STG);
            CP_COMMIT();
        }
        uint32_t stg = (uint32_t)st * S2_STG;
        uint32_t aA = sb + stg + S2_A + (wm + (mi & 1) * 8 + lane7) * 144 + (mi >> 1) * 16;
        uint32_t bB = sb + stg + S2_B + (wn + (mi >> 1) * 8 + lane7) * 144 + (mi & 1) * 16;
#pragma unroll
        for (int ks = 0; ks < 4; ks++) {
            uint32_t a0[4], a1[4];
            ldm4(a0, aA + ks * 32);
            ldm4(a1, aA + 2304 + ks * 32);
#pragma unroll
            for (int np = 0; np < 4; np++) {
                uint32_t bh[4];
                ldm4(bh, bB + np * 2304 + ks * 32);
                mmah(acc[0][2 * np], a0, bh);
                mmah(acc[0][2 * np + 1], a0, bh + 2);
                mmah(acc[1][2 * np], a1, bh);
                mmah(acc[1][2 * np + 1], a1, bh + 2);
            }
        }
        st = (st == 2) ? 0 : st + 1;
    }

    __syncthreads();
#pragma unroll
    for (int ms = 0; ms < 2; ms++)
#pragma unroll
        for (int h = 0; h < 2; h++) {
            int rr = wm + ms * 16 + qr + h * 8;
#pragma unroll
            for (int ns = 0; ns < 8; ns++) {
                int c = wn + ns * 8 + qc;
                *(uint32_t*)(smb + S2_C + rr * 528 + c * 2) =
                    packh2(fmaxf(acc[ms][ns][h * 2 + 0] + __ldg(ub1 + c), 0.f),
                           fmaxf(acc[ms][ns][h * 2 + 1] + __ldg(ub1 + c + 1), 0.f));
            }
        }
    for (int i = t; i < 2048; i += 512) {
        int n = i >> 5, c = i & 31;
        *(uint4*)(smb + S2_U2 + n * 528 + c * 16) = ((const uint4*)g_u2T)[i];
    }
    __syncthreads();

    int wm2 = (wid >> 2) * 32, wn2 = (wid & 3) * 16;
    float au[2][2][4];
#pragma unroll
    for (int m = 0; m < 2; m++)
#pragma unroll
        for (int n = 0; n < 2; n++)
#pragma unroll
            for (int j = 0; j < 4; j++) au[m][n][j] = 0.f;
    uint32_t aC = sb + S2_C + (wm2 + (mi & 1) * 8 + lane7) * 528 + (mi >> 1) * 16;
    uint32_t b2a = sb + S2_U2 + (wn2 + (mi >> 1) * 8 + lane7) * 528 + (mi & 1) * 16;
#pragma unroll 1
    for (int ks = 0; ks < 16; ks++) {
        uint32_t a0[4], a1[4], bh[4];
        ldm4(a0, aC + ks * 32);
        ldm4(a1, aC + 16 * 528 + ks * 32);
        ldm4(bh, b2a + ks * 32);
        mmah(au[0][0], a0, bh);
        mmah(au[0][1], a0, bh + 2);
        mmah(au[1][0], a1, bh);
        mmah(au[1][1], a1, bh + 2);
    }
#pragma unroll
    for (int mt = 0; mt < 2; mt++)
#pragma unroll
        for (int h = 0; h < 2; h++) {
            int rr = row0 + wm2 + mt * 16 + qr + h * 8;
#pragma unroll
            for (int nt = 0; nt < 2; nt++) {
                int c = wn2 + nt * 8 + qc;
                float2 v;
                v.x = au[mt][nt][h * 2 + 0] + __ldg(ub2 + c);
                v.y = au[mt][nt][h * 2 + 1] + __ldg(ub2 + c + 1);
                *(float2*)&g_U[(size_t)rr * 64 + c] = v;
            }
        }
}

// ======================================================================
// K3a/b + K4: out head (fp32)
// ======================================================================
__global__ void k3a_gemm(const float* __restrict__ w) {
    __shared__ float sUT[32 * 68];
    __shared__ float sWt[32 * 64];
    int t = threadIdx.x;
    int ty = t >> 4, tx = t & 15;
    int m0 = blockIdx.x * 64, n0 = blockIdx.y * 64, p = blockIdx.z;
    int k0 = p * 512;
    float acc[4][4];
#pragma unroll
    for (int i = 0; i < 4; i++)
#pragma unroll
        for (int j = 0; j < 4; j++) acc[i][j] = 0.f;
    for (int kt = 0; kt < 16; kt++) {
#pragma unroll
        for (int q = 0; q < 2; q++) {
            int f = q * 256 + t, r = f >> 3, c4 = f & 7;
            float4 v = *(const float4*)&g_U[(size_t)(m0 + r) * 4096 + k0 + kt * 32 + c4 * 4];
            sUT[(c4 * 4 + 0) * 68 + r] = v.x;
            sUT[(c4 * 4 + 1) * 68 + r] = v.y;
            sUT[(c4 * 4 + 2) * 68 + r] = v.z;
            sUT[(c4 * 4 + 3) * 68 + r] = v.w;
        }
#pragma unroll
        for (int q = 0; q < 2; q++) {
            int f = q * 256 + t, kr = f >> 4, c4 = f & 15;
            *(float4*)&sWt[kr * 64 + c4 * 4] =
                *(const float4*)&w[(size_t)(k0 + kt * 32 + kr) * 256 + n0 + c4 * 4];
        }
        __syncthreads();
#pragma unroll 4
        for (int k = 0; k < 32; k++) {
            float4 a = *(float4*)&sUT[k * 68 + ty * 4];
            float4 b = *(float4*)&sWt[k * 64 + tx * 4];
            float av[4] = {a.x, a.y, a.z, a.w};
            float bv[4] = {b.x, b.y, b.z, b.w};
#pragma unroll
            for (int i = 0; i < 4; i++)
#pragma unroll
                for (int j = 0; j < 4; j++) acc[i][j] = fmaf(av[i], bv[j], acc[i][j]);
        }
        __syncthreads();
    }
#pragma unroll
    for (int i = 0; i < 4; i++) {
        int m = m0 + ty * 4 + i;
        *(float4*)&g_P3[(size_t)p * 65536 + m * 256 + n0 + tx * 4] =
            make_float4(acc[i][0], acc[i][1], acc[i][2], acc[i][3]);
    }
}
__global__ void k3b_reduce(const float* __restrict__ b1) {
    int m = blockIdx.x, n = threadIdx.x;
    float acc = b1[n];
#pragma unroll
    for (int p = 0; p < 8; p++) acc += g_P3[p * 65536 + m * 256 + n];
    g_O1[m * 256 + n] = fmaxf(acc, 0.f);
}
__global__ void k4_final(const float* __restrict__ w2, const float* __restrict__ b2,
                         float* __restrict__ out) {
    __shared__ float sW[256];
    int t = threadIdx.x;
    sW[t] = w2[t];
    __syncthreads();
    int lane = t & 31, wid = t >> 5;
    int r0 = blockIdx.x * 32 + wid * 4;
    for (int r = r0; r < r0 + 4; r++) {
        float acc = 0.f;
#pragma unroll
        for (int k = lane; k < 256; k += 32) acc = fmaf(g_O1[r * 256 + k], sW[k], acc);
#pragma unroll
        for (int off = 16; off; off >>= 1) acc += __shfl_xor_sync(0xffffffffu, acc, off);
        if (lane == 0) out[r] = acc + b2[0];
    }
}

// ======================================================================
extern "C" void kernel_launch(void* const* d_in, const int* in_sizes, int n_in,
                              void* d_out, int out_size) {
    const float* node = (const float*)d_in[0];
    const float* ef   = (const float*)d_in[1];
    const float* mw1 = (const float*)d_in[3];
    const float* mb1 = (const float*)d_in[4];
    const float* mw2 = (const float*)d_in[5];
    const float* mb2 = (const float*)d_in[6];
    const float* mw3 = (const float*)d_in[7];
    const float* mb3 = (const float*)d_in[8];
    const float* uw1 = (const float*)d_in[9];
    const float* ub1 = (const float*)d_in[10];
    const float* uw2 = (const float*)d_in[11];
    const float* ub2 = (const float*)d_in[12];
    const float* ow1 = (const float*)d_in[13];
    const float* ob1 = (const float*)d_in[14];
    const float* ow2 = (const float*)d_in[15];
    const float* ob2 = (const float*)d_in[16];
    float* out = (float*)d_out;

    cudaFuncSetAttribute(k1, cudaFuncAttributeMaxDynamicSharedMemorySize, S1_SZ);
    cudaFuncSetAttribute(k2, cudaFuncAttributeMaxDynamicSharedMemorySize, S2_SZ);

    k0_pre<<<512, 128>>>(node, mw1, mb1);
    p_small<<<168, 256>>>(mw1, mw2, mw3, uw2);
    p_u1<<<dim3(128, 8), 256>>>(uw1);
    k1<<<2048, 512, S1_SZ>>>(ef, mb2, mb3);
    k2<<<128, 512, S2_SZ>>>(ub1, ub2);
    dim3 g3(4, 4, 8);
    k3a_gemm<<<g3, 256>>>(ow1);
    k3b_reduce<<<256, 256>>>(ob1);
    k4_final<<<8, 256>>>(ow2, ob2, out);
}

// round 17
// speedup vs baseline: 1.1347x; 1.0254x over previous
#include <cuda_runtime.h>
#include <cuda_fp16.h>
#include <cstdint>

#define NTOT 16384

// ---------------- scratch globals (no allocation) ----------------
__device__ float g_pre1[NTOT * 128];   // node part of msg layer1 (+b1), fp32
__device__ float g_P3[8 * 256 * 256];
__device__ float g_O1[256 * 256];
__device__ __align__(16) __half g_Uh[(size_t)256 * 4096];           // U (=out-head input), fp16
__device__ __align__(16) __half g_Ah[(size_t)NTOT * 4096];          // messages (permuted), fp16
__device__ __align__(16) __half g_w1T[128 * 16];
__device__ __align__(16) __half g_w2T[128 * 128];
__device__ __align__(16) __half g_w3T[64 * 128];
__device__ __align__(16) __half g_u1T[(size_t)256 * 4096];
__device__ __align__(16) __half g_u2T[64 * 256];
__device__ __align__(16) __half g_o1T[(size_t)256 * 4096];          // ow1 transposed, fp16

// ---------------- helpers ----------------
__device__ __forceinline__ uint32_t s2u(const void* p) {
    uint32_t a;
    asm("{ .reg .u64 t; cvta.to.shared.u64 t, %1; cvt.u32.u64 %0, t; }" : "=r"(a) : "l"(p));
    return a;
}
__device__ __forceinline__ void mmah(float* d, const uint32_t* a, const uint32_t* b) {
    asm volatile(
        "mma.sync.aligned.m16n8k16.row.col.f32.f16.f16.f32 "
        "{%0,%1,%2,%3}, {%4,%5,%6,%7}, {%8,%9}, {%0,%1,%2,%3};"
        : "+f"(d[0]), "+f"(d[1]), "+f"(d[2]), "+f"(d[3])
        : "r"(a[0]), "r"(a[1]), "r"(a[2]), "r"(a[3]), "r"(b[0]), "r"(b[1]));
}
__device__ __forceinline__ void ldm4(uint32_t* r, uint32_t a) {
    asm volatile("ldmatrix.sync.aligned.m8n8.x4.shared.b16 {%0,%1,%2,%3}, [%4];"
                 : "=r"(r[0]), "=r"(r[1]), "=r"(r[2]), "=r"(r[3]) : "r"(a));
}
__device__ __forceinline__ void cpa16(uint32_t s, const void* g) {
    asm volatile(
        "{ .reg .u64 p; cvta.to.global.u64 p, %1; cp.async.cg.shared.global [%0], [p], 16; }"
        :: "r"(s), "l"(g));
}
#define CP_COMMIT() asm volatile("cp.async.commit_group;" ::: "memory")
#define CP_WAIT1()  asm volatile("cp.async.wait_group 1;" ::: "memory")
#define CP_WAIT0()  asm volatile("cp.async.wait_group 0;" ::: "memory")
#define PSYNC(pid) asm volatile("bar.sync %0, 64;" :: "r"((pid) + 1) : "memory")

__device__ __forceinline__ uint32_t packh2(float a, float b) {
    __half2 h = __floats2half2_rn(a, b);
    return *(uint32_t*)&h;
}

// ======================================================================
// K0: pre1[n][j] = b1[j] + node[n][:] @ W1[0:32][j]   (fp32)
// ======================================================================
__global__ void k0_pre(const float* __restrict__ node, const float* __restrict__ w1,
                       const float* __restrict__ b1) {
    __shared__ float sW[32 * 128];
    __shared__ float sB[128];
    int t = threadIdx.x;
    for (int i = t; i < 32 * 128; i += 128) sW[i] = w1[i];
    sB[t] = b1[t];
    __syncthreads();
    int row0 = blockIdx.x * 32;
    for (int r = 0; r < 32; r++) {
        int n = row0 + r;
        const float* nd = node + n * 32;
        float acc = sB[t];
#pragma unroll
        for (int k = 0; k < 32; k++) acc = fmaf(__ldg(nd + k), sW[k * 128 + t], acc);
        g_pre1[n * 128 + t] = acc;
    }
}

// ======================================================================
// Prep kernels (all reference __device__ globals from DEVICE code only)
// ======================================================================
__global__ void p_small(const float* __restrict__ w1, const float* __restrict__ w2,
                        const float* __restrict__ w3, const float* __restrict__ uw2) {
    int i = blockIdx.x * 256 + threadIdx.x;
    if (i < 2048) {                                    // w1T_e [128 j][16 k] from rows 32..47
        int j = i >> 4, k = i & 15;
        g_w1T[i] = __float2half_rn(w1[(32 + k) * 128 + j]);
    } else if (i < 18432) {                            // w2T [128 j][128 k]
        int v = i - 2048, j = v >> 7, k = v & 127;
        g_w2T[v] = __float2half_rn(w2[k * 128 + j]);
    } else if (i < 26624) {                            // w3T [64 m][128 k]
        int v = i - 18432, m = v >> 7, k = v & 127;
        g_w3T[v] = __float2half_rn(w3[k * 64 + m]);
    } else if (i < 43008) {                            // u2T [64 n][256 k]
        int v = i - 26624, n = v >> 8, k = v & 255;
        g_u2T[v] = __float2half_rn(uw2[k * 64 + n]);
    }
}
__global__ void p_u1(const float* __restrict__ uw1) {  // [4096,256] -> g_u1T [256,4096]
    __shared__ float s[32][33];
    int k0 = blockIdx.x * 32, n0 = blockIdx.y * 32;
    int t = threadIdx.x, r8 = t >> 5, c = t & 31;
#pragma unroll
    for (int q = 0; q < 4; q++)
        s[q * 8 + r8][c] = uw1[(size_t)(k0 + q * 8 + r8) * 256 + n0 + c];
    __syncthreads();
#pragma unroll
    for (int q = 0; q < 4; q++) {
        int n = q * 8 + r8;
        g_u1T[(size_t)(n0 + n) * 4096 + k0 + c] = __float2half_rn(s[c][n]);
    }
}
__global__ void p_o1(const float* __restrict__ ow1) {  // [4096,256] -> g_o1T [256,4096]
    __shared__ float s[32][33];
    int k0 = blockIdx.x * 32, n0 = blockIdx.y * 32;
    int t = threadIdx.x, r8 = t >> 5, c = t & 31;
#pragma unroll
    for (int q = 0; q < 4; q++)
        s[q * 8 + r8][c] = ow1[(size_t)(k0 + q * 8 + r8) * 256 + n0 + c];
    __syncthreads();
#pragma unroll
    for (int q = 0; q < 4; q++) {
        int n = q * 8 + r8;
        g_o1T[(size_t)(n0 + n) * 4096 + k0 + c] = __float2half_rn(s[c][n]);
    }
}

// ======================================================================
// K1: fused msg MLP (R15: pair n-split + own-half register chaining)
// ======================================================================
#define S1_W1  0
#define S1_W2  6144
#define S1_W3  40960
#define S1_H1  58368
#define S1_A1  128000
#define S1_P1  140288
#define S1_B2  144384
#define S1_B3  144896
#define S1_SZ  145408

__global__ void __launch_bounds__(512, 1) k1(
    const float* __restrict__ ef,
    const float* __restrict__ b2, const float* __restrict__ b3)
{
    extern __shared__ char smb[];
    uint32_t sb = s2u(smb);
    int t = threadIdx.x, wid = t >> 5, lane = t & 31;
    int qr = lane >> 2, qc = (lane & 3) * 2;
    int lane7 = lane & 7, mi = lane >> 3;
    int pair = wid >> 1, nh = wid & 1;
    int m0 = pair * 32;

    for (int i = t; i < 256; i += 512) {
        int j = i >> 1, c = i & 1;
        *(uint4*)(smb + S1_W1 + j * 48 + c * 16) = ((const uint4*)g_w1T)[i];
    }
    for (int i = t; i < 2048; i += 512) {
        int j = i >> 4, c = i & 15;
        *(uint4*)(smb + S1_W2 + j * 272 + c * 16) = ((const uint4*)g_w2T)[i];
    }
    for (int i = t; i < 1024; i += 512) {
        int j = i >> 4, c = i & 15;
        *(uint4*)(smb + S1_W3 + j * 272 + c * 16) = ((const uint4*)g_w3T)[i];
    }
    if (t < 128) ((float*)(smb + S1_B2))[t] = b2[t];
    if (t < 64)  ((float*)(smb + S1_B3))[t] = b3[t];
    __syncthreads();

    const float* sB2  = (const float*)(smb + S1_B2);
    const float* sB3  = (const float*)(smb + S1_B3);
    const float* sP1p = (const float*)(smb + S1_P1 + pair * 512);

    uint32_t aA1 = sb + S1_A1 + (m0 + (mi & 1) * 8 + lane7) * 48 + (mi >> 1) * 16;
    uint32_t aH1 = sb + S1_H1 + (m0 + (mi & 1) * 8 + lane7) * 272 + (mi >> 1) * 16;
    uint32_t bW1 = sb + S1_W1 + (nh * 64 + (mi >> 1) * 8 + lane7) * 48 + (mi & 1) * 16;
    uint32_t bW2 = sb + S1_W2 + (nh * 64 + (mi >> 1) * 8 + lane7) * 272 + (mi & 1) * 16;
    uint32_t bW3 = sb + S1_W3 + (nh * 32 + (mi >> 1) * 8 + lane7) * 272 + (mi & 1) * 16;
    int ks_own0 = 4 * nh, ks_par0 = 4 * (1 - nh);

#pragma unroll 1
    for (int it = 0; it < 2; it++) {
        int g0 = (blockIdx.x * 2 + it) * 4;
        PSYNC(pair);

        {
            int r = t >> 1, hh = t & 1;
            const float4* ep = (const float4*)(ef + (size_t)(g0 * 64 + r) * 16) + hh * 2;
            float4 e0 = __ldg(ep), e1 = __ldg(ep + 1);
            uint32_t* de = (uint32_t*)(smb + S1_A1 + r * 48 + hh * 16);
            de[0] = packh2(e0.x, e0.y); de[1] = packh2(e0.z, e0.w);
            de[2] = packh2(e1.x, e1.y); de[3] = packh2(e1.z, e1.w);
            if (nh == 0) {
                int gP = g0 + (pair >> 1);
                float4 pv = __ldg((const float4*)(g_pre1 + gP * 128) + lane);
                *(float4*)(smb + S1_P1 + pair * 512 + lane * 16) = pv;
            }
        }
        PSYNC(pair);

        float acc[2][8][4];
#pragma unroll
        for (int m = 0; m < 2; m++)
#pragma unroll
            for (int n = 0; n < 8; n++)
#pragma unroll
                for (int j = 0; j < 4; j++) acc[m][n][j] = 0.f;
        {
            uint32_t a0[4], a1[4];
            ldm4(a0, aA1);
            ldm4(a1, aA1 + 16 * 48);
#pragma unroll
            for (int np = 0; np < 4; np++) {
                uint32_t bh[4];
                ldm4(bh, bW1 + np * 768);
                mmah(acc[0][2 * np], a0, bh);
                mmah(acc[0][2 * np + 1], a0, bh + 2);
                mmah(acc[1][2 * np], a1, bh);
                mmah(acc[1][2 * np + 1], a1, bh + 2);
            }
        }
        uint32_t aF[2][16];
#pragma unroll
        for (int mf = 0; mf < 2; mf++) {
            int r0 = m0 + mf * 16 + qr;
#pragma unroll
            for (int nt = 0; nt < 8; nt++) {
                int c0 = nh * 64 + nt * 8 + qc;
                float v0 = sP1p[c0], v1 = sP1p[c0 + 1];
                uint32_t lo = packh2(fmaxf(acc[mf][nt][0] + v0, 0.f),
                                     fmaxf(acc[mf][nt][1] + v1, 0.f));
                uint32_t hi = packh2(fmaxf(acc[mf][nt][2] + v0, 0.f),
                                     fmaxf(acc[mf][nt][3] + v1, 0.f));
                *(uint32_t*)(smb + S1_H1 + r0 * 272 + c0 * 2) = lo;
                *(uint32_t*)(smb + S1_H1 + (r0 + 8) * 272 + c0 * 2) = hi;
                aF[mf][(nt >> 1) * 4 + (nt & 1) * 2 + 0] = lo;
                aF[mf][(nt >> 1) * 4 + (nt & 1) * 2 + 1] = hi;
            }
        }

#pragma unroll
        for (int m = 0; m < 2; m++)
#pragma unroll
            for (int n = 0; n < 8; n++)
#pragma unroll
                for (int j = 0; j < 4; j++) acc[m][n][j] = 0.f;
#pragma unroll
        for (int ts = 0; ts < 4; ts++) {
            int ks = ks_own0 + ts;
#pragma unroll
            for (int np = 0; np < 4; np++) {
                uint32_t bh[4];
                ldm4(bh, bW2 + np * 4352 + ks * 32);
                mmah(acc[0][2 * np], &aF[0][ts * 4], bh);
                mmah(acc[0][2 * np + 1], &aF[0][ts * 4], bh + 2);
                mmah(acc[1][2 * np], &aF[1][ts * 4], bh);
                mmah(acc[1][2 * np + 1], &aF[1][ts * 4], bh + 2);
            }
        }
        PSYNC(pair);
#pragma unroll
        for (int ts = 0; ts < 4; ts++) {
            int ks = ks_par0 + ts;
            uint32_t p0[4], p1[4];
            ldm4(p0, aH1 + ks * 32);
            ldm4(p1, aH1 + 4352 + ks * 32);
#pragma unroll
            for (int np = 0; np < 4; np++) {
                uint32_t bh[4];
                ldm4(bh, bW2 + np * 4352 + ks * 32);
                mmah(acc[0][2 * np], p0, bh);
                mmah(acc[0][2 * np + 1], p0, bh + 2);
                mmah(acc[1][2 * np], p1, bh);
                mmah(acc[1][2 * np + 1], p1, bh + 2);
            }
        }
        PSYNC(pair);

#pragma unroll
        for (int mf = 0; mf < 2; mf++) {
            int r0 = m0 + mf * 16 + qr;
#pragma unroll
            for (int nt = 0; nt < 8; nt++) {
                int c0 = nh * 64 + nt * 8 + qc;
                float v0 = sB2[c0], v1 = sB2[c0 + 1];
                uint32_t lo = packh2(fmaxf(acc[mf][nt][0] + v0, 0.f),
                                     fmaxf(acc[mf][nt][1] + v1, 0.f));
                uint32_t hi = packh2(fmaxf(acc[mf][nt][2] + v0, 0.f),
                                     fmaxf(acc[mf][nt][3] + v1, 0.f));
                *(uint32_t*)(smb + S1_H1 + r0 * 272 + c0 * 2) = lo;
                *(uint32_t*)(smb + S1_H1 + (r0 + 8) * 272 + c0 * 2) = hi;
                aF[mf][(nt >> 1) * 4 + (nt & 1) * 2 + 0] = lo;
                aF[mf][(nt >> 1) * 4 + (nt & 1) * 2 + 1] = hi;
            }
        }

        float acc2[2][4][4];
#pragma unroll
        for (int m = 0; m < 2; m++)
#pragma unroll
            for (int n = 0; n < 4; n++)
#pragma unroll
                for (int j = 0; j < 4; j++) acc2[m][n][j] = 0.f;
#pragma unroll
        for (int ts = 0; ts < 4; ts++) {
            int ks = ks_own0 + ts;
#pragma unroll
            for (int np = 0; np < 2; np++) {
                uint32_t bh[4];
                ldm4(bh, bW3 + np * 4352 + ks * 32);
                mmah(acc2[0][2 * np], &aF[0][ts * 4], bh);
                mmah(acc2[0][2 * np + 1], &aF[0][ts * 4], bh + 2);
                mmah(acc2[1][2 * np], &aF[1][ts * 4], bh);
                mmah(acc2[1][2 * np + 1], &aF[1][ts * 4], bh + 2);
            }
        }
        PSYNC(pair);
#pragma unroll
        for (int ts = 0; ts < 4; ts++) {
            int ks = ks_par0 + ts;
            uint32_t p0[4], p1[4];
            ldm4(p0, aH1 + ks * 32);
            ldm4(p1, aH1 + 4352 + ks * 32);
#pragma unroll
            for (int np = 0; np < 2; np++) {
                uint32_t bh[4];
                ldm4(bh, bW3 + np * 4352 + ks * 32);
                mmah(acc2[0][2 * np], p0, bh);
                mmah(acc2[0][2 * np + 1], p0, bh + 2);
                mmah(acc2[1][2 * np], p1, bh);
                mmah(acc2[1][2 * np + 1], p1, bh + 2);
            }
        }
        {
            int g = g0 + (pair >> 1);
            size_t gb = ((size_t)((g >> 6) * 64)) * 4096 + (g & 63) * 64;
#pragma unroll
            for (int mf = 0; mf < 2; mf++)
#pragma unroll
                for (int h = 0; h < 2; h++) {
                    int d = (m0 + mf * 16 + qr + h * 8) & 63;
                    size_t base = gb + (size_t)d * 4096;
#pragma unroll
                    for (int nt = 0; nt < 4; nt++) {
                        int c0 = nh * 32 + nt * 8 + qc;
                        *(uint32_t*)(g_Ah + base + c0) =
                            packh2(acc2[mf][nt][h * 2 + 0] + sB3[c0],
                                   acc2[mf][nt][h * 2 + 1] + sB3[c0 + 1]);
                    }
                }
        }
    }
}

// ======================================================================
// K2: C = relu(A @ uw1 + ub1), fused U = C @ uw2 + ub2 -> g_Uh (fp16).
// ======================================================================
#define S2_A   0
#define S2_B   18432
#define S2_STG 55296
#define S2_C   0
#define S2_U2  67584
#define S2_SZ  165888

__global__ void __launch_bounds__(512, 1) k2(
    const float* __restrict__ ub1, const float* __restrict__ ub2)
{
    extern __shared__ char smb[];
    uint32_t sb = s2u(smb);
    int t = threadIdx.x, wid = t >> 5, lane = t & 31;
    int qr = lane >> 2, qc = (lane & 3) * 2;
    int lane7 = lane & 7, mi = lane >> 3;
    int row0 = blockIdx.x * 128;
    int wm = (wid >> 2) * 32, wn = (wid & 3) * 64;

    auto fill = [&](int kc, uint32_t stg) {
#pragma unroll
        for (int q = 0; q < 2; q++) {
            int i = q * 512 + t, r = i >> 3, c = i & 7;
            cpa16(sb + stg + S2_A + r * 144 + c * 16,
                  g_Ah + (size_t)(row0 + r) * 4096 + kc * 64 + c * 8);
        }
#pragma unroll
        for (int q = 0; q < 4; q++) {
            int i = q * 512 + t, n = i >> 3, c = i & 7;
            cpa16(sb + stg + S2_B + n * 144 + c * 16,
                  g_u1T + (size_t)n * 4096 + kc * 64 + c * 8);
        }
    };

    float acc[2][8][4];
#pragma unroll
    for (int m = 0; m < 2; m++)
#pragma unroll
        for (int n = 0; n < 8; n++)
#pragma unroll
            for (int j = 0; j < 4; j++) acc[m][n][j] = 0.f;

    fill(0, 0);
    CP_COMMIT();
    fill(1, S2_STG);
    CP_COMMIT();

    int st = 0;
#pragma unroll 1
    for (int kc = 0; kc < 64; kc++) {
        if (kc + 1 < 64) CP_WAIT1(); else CP_WAIT0();
        __syncthreads();
        if (kc + 2 < 64) {
            fill(kc + 2, (uint32_t)((kc + 2) % 3) * S2_STG);
            CP_COMMIT();
        }
        uint32_t stg = (uint32_t)st * S2_STG;
        uint32_t aA = sb + stg + S2_A + (wm + (mi & 1) * 8 + lane7) * 144 + (mi >> 1) * 16;
        uint32_t bB = sb + stg + S2_B + (wn + (mi >> 1) * 8 + lane7) * 144 + (mi & 1) * 16;
#pragma unroll
        for (int ks = 0; ks < 4; ks++) {
            uint32_t a0[4], a1[4];
            ldm4(a0, aA + ks * 32);
            ldm4(a1, aA + 2304 + ks * 32);
#pragma unroll
            for (int np = 0; np < 4; np++) {
                uint32_t bh[4];
                ldm4(bh, bB + np * 2304 + ks * 32);
                mmah(acc[0][2 * np], a0, bh);
                mmah(acc[0][2 * np + 1], a0, bh + 2);
                mmah(acc[1][2 * np], a1, bh);
                mmah(acc[1][2 * np + 1], a1, bh + 2);
            }
        }
        st = (st == 2) ? 0 : st + 1;
    }

    __syncthreads();
#pragma unroll
    for (int ms = 0; ms < 2; ms++)
#pragma unroll
        for (int h = 0; h < 2; h++) {
            int rr = wm + ms * 16 + qr + h * 8;
#pragma unroll
            for (int ns = 0; ns < 8; ns++) {
                int c = wn + ns * 8 + qc;
                *(uint32_t*)(smb + S2_C + rr * 528 + c * 2) =
                    packh2(fmaxf(acc[ms][ns][h * 2 + 0] + __ldg(ub1 + c), 0.f),
                           fmaxf(acc[ms][ns][h * 2 + 1] + __ldg(ub1 + c + 1), 0.f));
            }
        }
    for (int i = t; i < 2048; i += 512) {
        int n = i >> 5, c = i & 31;
        *(uint4*)(smb + S2_U2 + n * 528 + c * 16) = ((const uint4*)g_u2T)[i];
    }
    __syncthreads();

    int wm2 = (wid >> 2) * 32, wn2 = (wid & 3) * 16;
    float au[2][2][4];
#pragma unroll
    for (int m = 0; m < 2; m++)
#pragma unroll
        for (int n = 0; n < 2; n++)
#pragma unroll
            for (int j = 0; j < 4; j++) au[m][n][j] = 0.f;
    uint32_t aC = sb + S2_C + (wm2 + (mi & 1) * 8 + lane7) * 528 + (mi >> 1) * 16;
    uint32_t b2a = sb + S2_U2 + (wn2 + (mi >> 1) * 8 + lane7) * 528 + (mi & 1) * 16;
#pragma unroll 1
    for (int ks = 0; ks < 16; ks++) {
        uint32_t a0[4], a1[4], bh[4];
        ldm4(a0, aC + ks * 32);
        ldm4(a1, aC + 16 * 528 + ks * 32);
        ldm4(bh, b2a + ks * 32);
        mmah(au[0][0], a0, bh);
        mmah(au[0][1], a0, bh + 2);
        mmah(au[1][0], a1, bh);
        mmah(au[1][1], a1, bh + 2);
    }
#pragma unroll
    for (int mt = 0; mt < 2; mt++)
#pragma unroll
        for (int h = 0; h < 2; h++) {
            int rr = row0 + wm2 + mt * 16 + qr + h * 8;
#pragma unroll
            for (int nt = 0; nt < 2; nt++) {
                int c = wn2 + nt * 8 + qc;
                // U -> fp16 (g_Uh flat == out-head input [256, 4096])
                *(uint32_t*)(g_Uh + (size_t)rr * 64 + c) =
                    packh2(au[mt][nt][h * 2 + 0] + __ldg(ub2 + c),
                           au[mt][nt][h * 2 + 1] + __ldg(ub2 + c + 1));
            }
        }
}

// ======================================================================
// K3_tc: split-K fp16 tensor GEMM, P3[kz] = Uh[128m x 512k] @ o1T.
// grid (2 m, 8 kz) x 512 threads. Same mainloop skeleton as k2.
// ======================================================================
__global__ void __launch_bounds__(512, 1) k3_tc() {
    extern __shared__ char smb[];
    uint32_t sb = s2u(smb);
    int t = threadIdx.x, wid = t >> 5, lane = t & 31;
    int qr = lane >> 2, qc = (lane & 3) * 2;
    int lane7 = lane & 7, mi = lane >> 3;
    int row0 = blockIdx.x * 128;
    int kz = blockIdx.y;
    int kc0 = kz * 8;                       // 8 chunks of 64 = K 512
    int wm = (wid >> 2) * 32, wn = (wid & 3) * 64;

    auto fill = [&](int kc, uint32_t stg) {
#pragma unroll
        for (int q = 0; q < 2; q++) {
            int i = q * 512 + t, r = i >> 3, c = i & 7;
            cpa16(sb + stg + S2_A + r * 144 + c * 16,
                  g_Uh + (size_t)(row0 + r) * 4096 + kc * 64 + c * 8);
        }
#pragma unroll
        for (int q = 0; q < 4; q++) {
            int i = q * 512 + t, n = i >> 3, c = i & 7;
            cpa16(sb + stg + S2_B + n * 144 + c * 16,
                  g_o1T + (size_t)n * 4096 + kc * 64 + c * 8);
        }
    };

    float acc[2][8][4];
#pragma unroll
    for (int m = 0; m < 2; m++)
#pragma unroll
        for (int n = 0; n < 8; n++)
#pragma unroll
            for (int j = 0; j < 4; j++) acc[m][n][j] = 0.f;

    fill(kc0, 0);
    CP_COMMIT();
    fill(kc0 + 1, S2_STG);
    CP_COMMIT();

    int st = 0;
#pragma unroll 1
    for (int kq = 0; kq < 8; kq++) {
        if (kq + 1 < 8) CP_WAIT1(); else CP_WAIT0();
        __syncthreads();
        if (kq + 2 < 8) {
            fill(kc0 + kq + 2, (uint32_t)((kq + 2) % 3) * S2_STG);
            CP_COMMIT();
        }
        uint32_t stg = (uint32_t)st * S2_STG;
        uint32_t aA = sb + stg + S2_A + (wm + (mi & 1) * 8 + lane7) * 144 + (mi >> 1) * 16;
        uint32_t bB = sb + stg + S2_B + (wn + (mi >> 1) * 8 + lane7) * 144 + (mi & 1) * 16;
#pragma unroll
        for (int ks = 0; ks < 4; ks++) {
            uint32_t a0[4], a1[4];
            ldm4(a0, aA + ks * 32);
            ldm4(a1, aA + 2304 + ks * 32);
#pragma unroll
            for (int np = 0; np < 4; np++) {
                uint32_t bh[4];
                ldm4(bh, bB + np * 2304 + ks * 32);
                mmah(acc[0][2 * np], a0, bh);
                mmah(acc[0][2 * np + 1], a0, bh + 2);
                mmah(acc[1][2 * np], a1, bh);
                mmah(acc[1][2 * np + 1], a1, bh + 2);
            }
        }
        st = (st == 2) ? 0 : st + 1;
    }

    // write fp32 partials (bias+relu applied in k3b)
#pragma unroll
    for (int ms = 0; ms < 2; ms++)
#pragma unroll
        for (int h = 0; h < 2; h++) {
            int rr = row0 + wm + ms * 16 + qr + h * 8;
#pragma unroll
            for (int ns = 0; ns < 8; ns++) {
                int c = wn + ns * 8 + qc;
                float2 v;
                v.x = acc[ms][ns][h * 2 + 0];
                v.y = acc[ms][ns][h * 2 + 1];
                *(float2*)&g_P3[(size_t)kz * 65536 + rr * 256 + c] = v;
            }
        }
}

// ======================================================================
// K3b + K4: reduce + out head tail (fp32)
// ======================================================================
__global__ void k3b_reduce(const float* __restrict__ b1) {
    int m = blockIdx.x, n = threadIdx.x;
    float acc = b1[n];
#pragma unroll
    for (int p = 0; p < 8; p++) acc += g_P3[p * 65536 + m * 256 + n];
    g_O1[m * 256 + n] = fmaxf(acc, 0.f);
}
__global__ void k4_final(const float* __restrict__ w2, const float* __restrict__ b2,
                         float* __restrict__ out) {
    __shared__ float sW[256];
    int t = threadIdx.x;
    sW[t] = w2[t];
    __syncthreads();
    int lane = t & 31, wid = t >> 5;
    int r0 = blockIdx.x * 32 + wid * 4;
    for (int r = r0; r < r0 + 4; r++) {
        float acc = 0.f;
#pragma unroll
        for (int k = lane; k < 256; k += 32) acc = fmaf(g_O1[r * 256 + k], sW[k], acc);
#pragma unroll
        for (int off = 16; off; off >>= 1) acc += __shfl_xor_sync(0xffffffffu, acc, off);
        if (lane == 0) out[r] = acc + b2[0];
    }
}

// ======================================================================
extern "C" void kernel_launch(void* const* d_in, const int* in_sizes, int n_in,
                              void* d_out, int out_size) {
    const float* node = (const float*)d_in[0];
    const float* ef   = (const float*)d_in[1];
    const float* mw1 = (const float*)d_in[3];
    const float* mb1 = (const float*)d_in[4];
    const float* mw2 = (const float*)d_in[5];
    const float* mb2 = (const float*)d_in[6];
    const float* mw3 = (const float*)d_in[7];
    const float* mb3 = (const float*)d_in[8];
    const float* uw1 = (const float*)d_in[9];
    const float* ub1 = (const float*)d_in[10];
    const float* uw2 = (const float*)d_in[11];
    const float* ub2 = (const float*)d_in[12];
    const float* ow1 = (const float*)d_in[13];
    const float* ob1 = (const float*)d_in[14];
    const float* ow2 = (const float*)d_in[15];
    const float* ob2 = (const float*)d_in[16];
    float* out = (float*)d_out;

    cudaFuncSetAttribute(k1, cudaFuncAttributeMaxDynamicSharedMemorySize, S1_SZ);
    cudaFuncSetAttribute(k2, cudaFuncAttributeMaxDynamicSharedMemorySize, S2_SZ);
    cudaFuncSetAttribute(k3_tc, cudaFuncAttributeMaxDynamicSharedMemorySize, S2_SZ);

    k0_pre<<<512, 128>>>(node, mw1, mb1);
    p_small<<<168, 256>>>(mw1, mw2, mw3, uw2);
    p_u1<<<dim3(128, 8), 256>>>(uw1);
    p_o1<<<dim3(128, 8), 256>>>(ow1);
    k1<<<2048, 512, S1_SZ>>>(ef, mb2, mb3);
    k2<<<128, 512, S2_SZ>>>(ub1, ub2);
    k3_tc<<<dim3(2, 8), 512, S2_SZ>>>();
    k3b_reduce<<<256, 256>>>(ob1);
    k4_final<<<8, 256>>>(ow2, ob2, out);
}